// round 3
// baseline (speedup 1.0000x reference)
#include <cuda_runtime.h>

#define B_ 16
#define L_ 576
#define H_ 12
#define D_ 64
#define M_ 8
#define NUM_STAB 1e-3f
#define RATIO 0.35355339059327373f   /* 1/sqrt(M) */

typedef unsigned long long ull;

// -------- scratch (device globals: no allocation allowed) --------
__device__ float g_qp[B_ * H_ * L_ * M_];   // q' features, [B,H,L,M]
__device__ float g_kp[B_ * H_ * L_ * M_];   // k' features, [B,H,L,M]
__device__ float g_cmp[8 * H_ * L_];        // partial column sums of mask
__device__ float g_ks[B_ * H_ * M_];        // ks_sum[b,h,m]

// -------- packed f32x2 helpers (sm_100+) --------
__device__ __forceinline__ ull mul2(ull a, ull b) {
    ull r;
    asm("mul.rn.f32x2 %0, %1, %2;" : "=l"(r) : "l"(a), "l"(b));
    return r;
}
__device__ __forceinline__ void ffma2(ull& d, ull a, ull b) {
    asm("fma.rn.f32x2 %0, %1, %2, %0;" : "+l"(d) : "l"(a), "l"(b));
}
__device__ __forceinline__ float2 unpack2(ull v) {
    float2 r;
    asm("mov.b64 {%0, %1}, %2;" : "=f"(r.x), "=f"(r.y) : "l"(v));
    return r;
}

// ============================================================
// Kernel 1: ReLU random features. blockIdx.y: 0->query, 1->key.
// Block 256 = 32 rows x 8 m-threads; rows staged in smem coalesced.
// ============================================================
__global__ void __launch_bounds__(256) feat_kernel(const float* __restrict__ q,
                                                   const float* __restrict__ k,
                                                   const float* __restrict__ proj) {
    __shared__ float xs[32][68];
    __shared__ float ps[8][68];
    int tid = threadIdx.x;
    const float* x = blockIdx.y ? k : q;
    float* o       = blockIdx.y ? g_kp : g_qp;

    // proj is M*D = 512 floats; 256 threads x float2 covers all of it.
    {
        float2 pv = ((const float2*)proj)[tid];
        ps[tid >> 5][(tid & 31) * 2]     = pv.x;
        ps[tid >> 5][(tid & 31) * 2 + 1] = pv.y;
    }
    int row0 = blockIdx.x * 32;
#pragma unroll
    for (int itr = 0; itr < 2; itr++) {
        int idx = itr * 256 + tid;
        int r = idx >> 4, c4 = idx & 15;
        float4 val = *(const float4*)(x + (size_t)(row0 + r) * D_ + c4 * 4);
        *(float4*)&xs[r][c4 * 4] = val;
    }
    __syncthreads();

    int r = tid >> 3, m = tid & 7;
    float acc = 0.0f;
#pragma unroll
    for (int i = 0; i < 16; i++) {
        float4 a = *(const float4*)&xs[r][i * 4];
        float4 b = *(const float4*)&ps[m][i * 4];
        acc += a.x * b.x + a.y * b.y + a.z * b.z + a.w * b.w;
    }
    int grow = row0 + r;                 // (b*L + l)*H + h
    int b = grow / (L_ * H_);
    int l = (grow / H_) % L_;
    int h = grow % H_;
    o[(((size_t)(b * H_ + h) * L_ + l) << 3) + m] = fmaxf(RATIO * acc, 0.0f) + NUM_STAB;
}

// ============================================================
// Kernel 2: partial column sums of mask: g_cmp[ch,h,j] = sum_{i in chunk} mask[h,i,j]
// grid (8 chunks, H), block 576 (one thread per j) -> 96 CTAs, coalesced.
// ============================================================
__global__ void __launch_bounds__(576) cmask_part_kernel(const float* __restrict__ mask) {
    int j  = threadIdx.x;
    int h  = blockIdx.y, ch = blockIdx.x;
    const float* mp = mask + ((size_t)h * L_ + ch * 72) * L_ + j;
    float s = 0.0f;
#pragma unroll 8
    for (int i = 0; i < 72; i++) s += mp[(size_t)i * L_];
    g_cmp[(ch * H_ + h) * L_ + j] = s;
}

// ============================================================
// Kernel 3: ks_sum[b,h,m] = sum_j cmask[h,j] * k'[b,h,j,m]
// ============================================================
__global__ void __launch_bounds__(64) ks_kernel() {
    int bh = blockIdx.x;
    int h  = bh % H_;
    int tid = threadIdx.x;
    __shared__ float red[64][8];

    float acc[8];
#pragma unroll
    for (int m = 0; m < 8; m++) acc[m] = 0.0f;

    for (int j = tid; j < L_; j += 64) {
        float c = 0.0f;
#pragma unroll
        for (int ch = 0; ch < 8; ch++) c += g_cmp[(ch * H_ + h) * L_ + j];
        const float4* kr = (const float4*)(g_kp + ((size_t)bh * L_ + j) * 8);
        float4 a = kr[0], bb = kr[1];
        acc[0] += c * a.x;  acc[1] += c * a.y;
        acc[2] += c * a.z;  acc[3] += c * a.w;
        acc[4] += c * bb.x; acc[5] += c * bb.y;
        acc[6] += c * bb.z; acc[7] += c * bb.w;
    }
#pragma unroll
    for (int m = 0; m < 8; m++) red[tid][m] = acc[m];
    __syncthreads();
    if (tid < 8) {
        float s = 0.0f;
        for (int i = 0; i < 64; i++) s += red[i][tid];
        g_ks[bh * 8 + tid] = s;
    }
}

// ============================================================
// Kernel 4: fused masked linear attention.
// grid (9, H, B), block 64. CTA tile: 64 rows x 64 cols per j-tile.
// Mask staged coalesced into quad-interleaved A buffer (in-place A=mask*S).
// AV uses f32x2 with lanes split over k (even/odd), summed at the end.
// ============================================================
__global__ void __launch_bounds__(64, 5)
attn_kernel(const float* __restrict__ v,
            const float* __restrict__ mask,
            float* __restrict__ out) {
    const int it = blockIdx.x, h = blockIdx.y, b = blockIdx.z;
    const int i0 = it * 64;
    const int bh = b * H_ + h;
    const int tid = threadIdx.x;
    const int ty = tid >> 3, tx = tid & 7;

    __shared__ float Aq[16][65][4];   // Aq[kq][i][kk] = A[i][4kq+kk] (also holds mask tile)
    __shared__ ull   Vp[32][64];      // Vp[kp][c] = (V[2kp][c], V[2kp+1][c])
    __shared__ float Qs[64][8];
    __shared__ float Ks[64][8];
    __shared__ float KSs[8];

    // Q' tile + ks_sum
    {
        const float4* src = (const float4*)(g_qp + ((size_t)bh * L_ + i0) * 8);
        ((float4*)Qs)[tid]      = src[tid];
        ((float4*)Qs)[tid + 64] = src[tid + 64];
    }
    if (tid < 8) KSs[tid] = g_ks[bh * 8 + tid];

    ull acc[8][8];
#pragma unroll
    for (int r = 0; r < 8; r++)
#pragma unroll
        for (int c = 0; c < 8; c++) acc[r][c] = 0ULL;

    const float* maskh = mask + (size_t)h * L_ * L_ + (size_t)i0 * L_;
    const float* vbase = v + ((size_t)b * L_ * H_ + h) * D_;

    for (int jt = 0; jt < L_ / 64; jt++) {
        const int j0 = jt * 64;
        __syncthreads();   // previous AV reads done before overwrite

        // ---- mask tile -> Aq, coalesced (16 threads per row) ----
#pragma unroll
        for (int itr = 0; itr < 16; itr++) {
            int idx = itr * 64 + tid;
            int i = idx >> 4, t = idx & 15;
            float4 mv = __ldg((const float4*)(maskh + (size_t)i * L_ + j0 + t * 4));
            *(float4*)&Aq[t][i][0] = mv;
        }
        // ---- V tile -> Vp (k-pair packed, interleaved columns) ----
#pragma unroll
        for (int itr = 0; itr < 16; itr++) {
            int idx = itr * 64 + tid;
            int r = idx >> 4, d4 = idx & 15;
            float4 vv = __ldg((const float4*)(vbase + (size_t)(j0 + r) * (H_ * D_) + d4 * 4));
            float* vp = (float*)&Vp[r >> 1][0] + (r & 1);
            vp[(d4 * 4 + 0) * 2] = vv.x;
            vp[(d4 * 4 + 1) * 2] = vv.y;
            vp[(d4 * 4 + 2) * 2] = vv.z;
            vp[(d4 * 4 + 3) * 2] = vv.w;
        }
        // ---- K' tile ----
        {
            const float4* ksrc = (const float4*)(g_kp + ((size_t)bh * L_ + j0) * 8);
            ((float4*)Ks)[2 * tid]     = ksrc[2 * tid];
            ((float4*)Ks)[2 * tid + 1] = ksrc[2 * tid + 1];
        }
        __syncthreads();

        // ---- S phase: thread owns column j = tid; A = mask * (q'.k') in place ----
        {
            ulonglong2 kA = *(const ulonglong2*)&Ks[tid][0];
            ulonglong2 kB = *(const ulonglong2*)&Ks[tid][4];
            float* ac = &Aq[tid >> 2][0][tid & 3];
#pragma unroll 4
            for (int i = 0; i < 64; i++) {
                ulonglong2 qA = *(const ulonglong2*)&Qs[i][0];
                ulonglong2 qB = *(const ulonglong2*)&Qs[i][4];
                ull s2 = mul2(qA.x, kA.x);
                ffma2(s2, qA.y, kA.y);
                ffma2(s2, qB.x, kB.x);
                ffma2(s2, qB.y, kB.y);
                float2 p = unpack2(s2);
                ac[i * 4] = (p.x + p.y) * ac[i * 4];
            }
        }
        __syncthreads();

        // ---- AV phase: O[ty+8rr][tx+8cc] += sum_k A*V, lanes = (even k, odd k) ----
#pragma unroll 1
        for (int kq = 0; kq < 16; kq++) {
            ulonglong2 a[8];
#pragma unroll
            for (int rr = 0; rr < 8; rr++)
                a[rr] = *(const ulonglong2*)&Aq[kq][ty + 8 * rr][0];
            const ull* v0 = &Vp[2 * kq][tx];
            const ull* v1 = &Vp[2 * kq + 1][tx];
#pragma unroll
            for (int cc = 0; cc < 8; cc++) {
                ull v01 = v0[cc * 8];
                ull v23 = v1[cc * 8];
#pragma unroll
                for (int rr = 0; rr < 8; rr++) {
                    ffma2(acc[rr][cc], a[rr].x, v01);
                    ffma2(acc[rr][cc], a[rr].y, v23);
                }
            }
        }
    }

    // ---- epilogue: normalizer + store ----
    float* obase = out + (((size_t)b * L_ + i0) * H_ + h) * D_;
#pragma unroll
    for (int rr = 0; rr < 8; rr++) {
        int rl = ty + 8 * rr;
        float n = 0.0f;
#pragma unroll
        for (int m = 0; m < 8; m++) n += Qs[rl][m] * KSs[m];
        float rn = 1.0f / n;
        float* op = obase + (size_t)rl * (H_ * D_) + tx;
#pragma unroll
        for (int cc = 0; cc < 8; cc++) {
            float2 p = unpack2(acc[rr][cc]);
            op[cc * 8] = (p.x + p.y) * rn;
        }
    }
}

// ============================================================
extern "C" void kernel_launch(void* const* d_in, const int* in_sizes, int n_in,
                              void* d_out, int out_size) {
    const float* q    = (const float*)d_in[0];
    const float* k    = (const float*)d_in[1];
    const float* v    = (const float*)d_in[2];
    const float* proj = (const float*)d_in[3];
    const float* mask = (const float*)d_in[4];
    float* out = (float*)d_out;

    // 1) ReLU features for q and k
    {
        dim3 grid(B_ * L_ * H_ / 32, 2);
        feat_kernel<<<grid, 256>>>(q, k, proj);
    }
    // 2) mask partial column sums
    {
        dim3 grid(8, H_);
        cmask_part_kernel<<<grid, 576>>>(mask);
    }
    // 3) ks_sum
    ks_kernel<<<B_ * H_, 64>>>();
    // 4) fused masked linear attention
    {
        dim3 grid(L_ / 64, H_, B_);
        attn_kernel<<<grid, 64>>>(v, mask, out);
    }
}

// round 4
// speedup vs baseline: 1.4876x; 1.4876x over previous
#include <cuda_runtime.h>

#define B_ 16
#define L_ 576
#define H_ 12
#define D_ 64
#define M_ 8
#define NUM_STAB 1e-3f
#define RATIO 0.35355339059327373f   /* 1/sqrt(M) */

typedef unsigned long long ull;

// -------- scratch (device globals: no allocation allowed) --------
__device__ float g_qp[B_ * H_ * L_ * M_];   // q' features, [B,H,L,M]
__device__ float g_kp[B_ * H_ * L_ * M_];   // k' features, [B,H,L,M]
__device__ float g_cmp[8 * H_ * L_];        // partial column sums of mask
__device__ float g_ks[B_ * H_ * M_];        // ks_sum[b,h,m]

// -------- packed f32x2 helpers (sm_100+) --------
__device__ __forceinline__ ull mul2(ull a, ull b) {
    ull r;
    asm("mul.rn.f32x2 %0, %1, %2;" : "=l"(r) : "l"(a), "l"(b));
    return r;
}
__device__ __forceinline__ void ffma2(ull& d, ull a, ull b) {
    asm("fma.rn.f32x2 %0, %1, %2, %0;" : "+l"(d) : "l"(a), "l"(b));
}
__device__ __forceinline__ ull pack2(float x, float y) {
    ull r;
    asm("mov.b64 %0, {%1, %2};" : "=l"(r) : "f"(x), "f"(y));
    return r;
}
__device__ __forceinline__ float2 unpack2(ull v) {
    float2 r;
    asm("mov.b64 {%0, %1}, %2;" : "=f"(r.x), "=f"(r.y) : "l"(v));
    return r;
}

// ============================================================
// Kernel 1: ReLU random features. blockIdx.y: 0->query, 1->key.
// ============================================================
__global__ void __launch_bounds__(256) feat_kernel(const float* __restrict__ q,
                                                   const float* __restrict__ k,
                                                   const float* __restrict__ proj) {
    __shared__ float xs[32][68];
    __shared__ float ps[8][68];
    int tid = threadIdx.x;
    const float* x = blockIdx.y ? k : q;
    float* o       = blockIdx.y ? g_kp : g_qp;

    {
        float2 pv = ((const float2*)proj)[tid];
        ps[tid >> 5][(tid & 31) * 2]     = pv.x;
        ps[tid >> 5][(tid & 31) * 2 + 1] = pv.y;
    }
    int row0 = blockIdx.x * 32;
#pragma unroll
    for (int itr = 0; itr < 2; itr++) {
        int idx = itr * 256 + tid;
        int r = idx >> 4, c4 = idx & 15;
        float4 val = *(const float4*)(x + (size_t)(row0 + r) * D_ + c4 * 4);
        *(float4*)&xs[r][c4 * 4] = val;
    }
    __syncthreads();

    int r = tid >> 3, m = tid & 7;
    float acc = 0.0f;
#pragma unroll
    for (int i = 0; i < 16; i++) {
        float4 a = *(const float4*)&xs[r][i * 4];
        float4 b = *(const float4*)&ps[m][i * 4];
        acc += a.x * b.x + a.y * b.y + a.z * b.z + a.w * b.w;
    }
    int grow = row0 + r;
    int b = grow / (L_ * H_);
    int l = (grow / H_) % L_;
    int h = grow % H_;
    o[(((size_t)(b * H_ + h) * L_ + l) << 3) + m] = fmaxf(RATIO * acc, 0.0f) + NUM_STAB;
}

// ============================================================
// Kernel 2: partial column sums of mask
// ============================================================
__global__ void __launch_bounds__(576) cmask_part_kernel(const float* __restrict__ mask) {
    int j  = threadIdx.x;
    int h  = blockIdx.y, ch = blockIdx.x;
    const float* mp = mask + ((size_t)h * L_ + ch * 72) * L_ + j;
    float s = 0.0f;
#pragma unroll 8
    for (int i = 0; i < 72; i++) s += mp[(size_t)i * L_];
    g_cmp[(ch * H_ + h) * L_ + j] = s;
}

// ============================================================
// Kernel 3: ks_sum[b,h,m] = sum_j cmask[h,j] * k'[b,h,j,m]
// ============================================================
__global__ void __launch_bounds__(64) ks_kernel() {
    int bh = blockIdx.x;
    int h  = bh % H_;
    int tid = threadIdx.x;
    __shared__ float red[64][8];

    float acc[8];
#pragma unroll
    for (int m = 0; m < 8; m++) acc[m] = 0.0f;

    for (int j = tid; j < L_; j += 64) {
        float c = 0.0f;
#pragma unroll
        for (int ch = 0; ch < 8; ch++) c += g_cmp[(ch * H_ + h) * L_ + j];
        const float4* kr = (const float4*)(g_kp + ((size_t)bh * L_ + j) * 8);
        float4 a = kr[0], bb = kr[1];
        acc[0] += c * a.x;  acc[1] += c * a.y;
        acc[2] += c * a.z;  acc[3] += c * a.w;
        acc[4] += c * bb.x; acc[5] += c * bb.y;
        acc[6] += c * bb.z; acc[7] += c * bb.w;
    }
#pragma unroll
    for (int m = 0; m < 8; m++) red[tid][m] = acc[m];
    __syncthreads();
    if (tid < 8) {
        float s = 0.0f;
        for (int i = 0; i < 64; i++) s += red[i][tid];
        g_ks[bh * 8 + tid] = s;
    }
}

// ============================================================
// Kernel 4: fused masked linear attention, 128 threads/CTA.
// Tile 64 i-rows x 64 j-cols per step; thread AV tile 4 rows x 8 cols.
// S phase: 2 threads per column (32 i each), K' column from gmem,
// f32x2 dot, float4 batched STS into As[j][i].
// ============================================================
__global__ void __launch_bounds__(128, 5)
attn_kernel(const float* __restrict__ v,
            const float* __restrict__ mask,
            float* __restrict__ out) {
    const int it = blockIdx.x, h = blockIdx.y, b = blockIdx.z;
    const int i0 = it * 64;
    const int bh = b * H_ + h;
    const int tid = threadIdx.x;
    const int ty = tid >> 3, tx = tid & 7;     // AV mapping: rows 4*ty, cols 8*tx
    const int sj = tid & 63, ih = tid >> 6;    // S mapping: column sj, i-half ih

    __shared__ float Qs[64][8];
    __shared__ float As[64][68];   // As[j][i]
    __shared__ float Vs[64][68];   // Vs[k][d]
    __shared__ float KSs[8];

    // stage Q' tile (contiguous) + ks_sum
    ((float4*)Qs)[tid] = ((const float4*)(g_qp + ((size_t)bh * L_ + i0) * 8))[tid];
    if (tid < 8) KSs[tid] = g_ks[bh * 8 + tid];

    ull acc[4][4];
#pragma unroll
    for (int r = 0; r < 4; r++)
#pragma unroll
        for (int c = 0; c < 4; c++) acc[r][c] = 0ULL;

    const float* maskh = mask + (size_t)h * L_ * L_ + (size_t)(i0 + ih * 32) * L_;
    const float* vbase = v + ((size_t)b * L_ * H_ + h) * D_;
    const float* kpb   = g_kp + ((size_t)bh * L_) * 8;

    for (int jt = 0; jt < L_ / 64; jt++) {
        const int j0 = jt * 64;
        __syncthreads();   // previous AV reads of As/Vs complete

        // ---- stage V tile: 64 rows x 64 floats, coalesced ----
#pragma unroll
        for (int itr = 0; itr < 8; itr++) {
            int idx = itr * 128 + tid;
            int r = idx >> 4, d4 = idx & 15;
            float4 vv = __ldg((const float4*)(vbase + (size_t)(j0 + r) * (H_ * D_) + d4 * 4));
            *(float4*)&Vs[r][d4 * 4] = vv;
        }

        // ---- K' column for this thread, straight from gmem (coalesced) ----
        ulonglong2 kA = *(const ulonglong2*)(kpb + (size_t)(j0 + sj) * 8);
        ulonglong2 kB = *(const ulonglong2*)(kpb + (size_t)(j0 + sj) * 8 + 4);

        // ---- S phase: A[i][j] = mask[i][j] * (q'_i . k'_j), 32 i's per thread ----
        {
            const float* mc = maskh + j0 + sj;
            float* arow = &As[sj][ih * 32];
#pragma unroll
            for (int ib = 0; ib < 32; ib += 4) {
                float mv0 = __ldg(mc + (size_t)(ib + 0) * L_);
                float mv1 = __ldg(mc + (size_t)(ib + 1) * L_);
                float mv2 = __ldg(mc + (size_t)(ib + 2) * L_);
                float mv3 = __ldg(mc + (size_t)(ib + 3) * L_);
                float mvv[4] = {mv0, mv1, mv2, mv3};
                float4 sv;
                float* sp = &sv.x;
#pragma unroll
                for (int ii = 0; ii < 4; ii++) {
                    const ulonglong2* qr = (const ulonglong2*)&Qs[ih * 32 + ib + ii][0];
                    ulonglong2 qA = qr[0];
                    ulonglong2 qB = qr[1];
                    ull s2 = mul2(qA.x, kA.x);
                    ffma2(s2, qA.y, kA.y);
                    ffma2(s2, qB.x, kB.x);
                    ffma2(s2, qB.y, kB.y);
                    float2 p = unpack2(s2);
                    sp[ii] = (p.x + p.y) * mvv[ii];
                }
                *(float4*)(arow + ib) = sv;   // aligned: 68*sj + ih*32 + ib
            }
        }
        __syncthreads();

        // ---- AV phase: O[4ty+rr][8tx+cc] += sum_k A * V ----
#pragma unroll 8
        for (int k = 0; k < 64; k++) {
            float4 a4 = *(const float4*)&As[k][4 * ty];
            ulonglong2 v01 = *(const ulonglong2*)&Vs[k][8 * tx];
            ulonglong2 v23 = *(const ulonglong2*)&Vs[k][8 * tx + 4];
            float ar[4] = {a4.x, a4.y, a4.z, a4.w};
#pragma unroll
            for (int rr = 0; rr < 4; rr++) {
                ull a2 = pack2(ar[rr], ar[rr]);
                ffma2(acc[rr][0], a2, v01.x);
                ffma2(acc[rr][1], a2, v01.y);
                ffma2(acc[rr][2], a2, v23.x);
                ffma2(acc[rr][3], a2, v23.y);
            }
        }
    }

    // ---- epilogue: normalizer + store ----
    float* obase = out + (((size_t)b * L_ + i0) * H_ + h) * D_;
#pragma unroll
    for (int rr = 0; rr < 4; rr++) {
        int rl = 4 * ty + rr;
        float n = 0.0f;
#pragma unroll
        for (int m = 0; m < 8; m++) n += Qs[rl][m] * KSs[m];
        float rn = 1.0f / n;
        float2 p0 = unpack2(acc[rr][0]);
        float2 p1 = unpack2(acc[rr][1]);
        float2 p2 = unpack2(acc[rr][2]);
        float2 p3 = unpack2(acc[rr][3]);
        float* op = obase + (size_t)rl * (H_ * D_) + 8 * tx;
        *(float4*)op       = make_float4(p0.x * rn, p0.y * rn, p1.x * rn, p1.y * rn);
        *(float4*)(op + 4) = make_float4(p2.x * rn, p2.y * rn, p3.x * rn, p3.y * rn);
    }
}

// ============================================================
extern "C" void kernel_launch(void* const* d_in, const int* in_sizes, int n_in,
                              void* d_out, int out_size) {
    const float* q    = (const float*)d_in[0];
    const float* k    = (const float*)d_in[1];
    const float* v    = (const float*)d_in[2];
    const float* proj = (const float*)d_in[3];
    const float* mask = (const float*)d_in[4];
    float* out = (float*)d_out;

    {
        dim3 grid(B_ * L_ * H_ / 32, 2);
        feat_kernel<<<grid, 256>>>(q, k, proj);
    }
    {
        dim3 grid(8, H_);
        cmask_part_kernel<<<grid, 576>>>(mask);
    }
    ks_kernel<<<B_ * H_, 64>>>();
    {
        dim3 grid(L_ / 64, H_, B_);
        attn_kernel<<<grid, 128>>>(v, mask, out);
    }
}

// round 6
// speedup vs baseline: 2.7206x; 1.8289x over previous
#include <cuda_runtime.h>
#include <cuda_bf16.h>
#include <cstdint>

#define B_ 16
#define L_ 576
#define H_ 12
#define D_ 64
#define M_ 8
#define NUM_STAB 1e-3f
#define RATIO 0.35355339059327373f   /* 1/sqrt(M) */
#define PAD 72

typedef unsigned long long ull;

// -------- scratch (device globals: no allocation allowed) --------
__device__ float g_qp[B_ * H_ * L_ * M_];   // q' features, [B,H,L,M]
__device__ float g_kp[B_ * H_ * L_ * M_];   // k' features, [B,H,L,M]
__device__ float g_cmp[8 * H_ * L_];        // partial column sums of mask
__device__ float g_ks[B_ * H_ * M_];        // ks_sum[b,h,m]

// -------- f32x2 helpers --------
__device__ __forceinline__ ull mul2(ull a, ull b) {
    ull r; asm("mul.rn.f32x2 %0, %1, %2;" : "=l"(r) : "l"(a), "l"(b)); return r;
}
__device__ __forceinline__ void ffma2(ull& d, ull a, ull b) {
    asm("fma.rn.f32x2 %0, %1, %2, %0;" : "+l"(d) : "l"(a), "l"(b));
}
__device__ __forceinline__ float2 unpack2(ull v) {
    float2 r; asm("mov.b64 {%0, %1}, %2;" : "=f"(r.x), "=f"(r.y) : "l"(v)); return r;
}

// -------- mma helpers (arch-neutral sm_80+ PTX) --------
__device__ __forceinline__ void ldmx4(uint32_t addr, uint32_t* r) {
    asm volatile("ldmatrix.sync.aligned.m8n8.x4.shared.b16 {%0,%1,%2,%3}, [%4];"
                 : "=r"(r[0]), "=r"(r[1]), "=r"(r[2]), "=r"(r[3]) : "r"(addr));
}
__device__ __forceinline__ void ldmx2t(uint32_t addr, uint32_t* r) {
    asm volatile("ldmatrix.sync.aligned.m8n8.x2.trans.shared.b16 {%0,%1}, [%2];"
                 : "=r"(r[0]), "=r"(r[1]) : "r"(addr));
}
__device__ __forceinline__ void mma16816(float* c, const uint32_t* a, const uint32_t* b) {
    asm volatile("mma.sync.aligned.m16n8k16.row.col.f32.bf16.bf16.f32 "
                 "{%0,%1,%2,%3}, {%4,%5,%6,%7}, {%8,%9}, {%0,%1,%2,%3};"
                 : "+f"(c[0]), "+f"(c[1]), "+f"(c[2]), "+f"(c[3])
                 : "r"(a[0]), "r"(a[1]), "r"(a[2]), "r"(a[3]), "r"(b[0]), "r"(b[1]));
}

// ============================================================
// Kernel 1: ReLU random features (proven in r4)
// ============================================================
__global__ void __launch_bounds__(256) feat_kernel(const float* __restrict__ q,
                                                   const float* __restrict__ k,
                                                   const float* __restrict__ proj) {
    __shared__ float xs[32][68];
    __shared__ float ps[8][68];
    int tid = threadIdx.x;
    const float* x = blockIdx.y ? k : q;
    float* o       = blockIdx.y ? g_kp : g_qp;
    {
        float2 pv = ((const float2*)proj)[tid];
        ps[tid >> 5][(tid & 31) * 2]     = pv.x;
        ps[tid >> 5][(tid & 31) * 2 + 1] = pv.y;
    }
    int row0 = blockIdx.x * 32;
#pragma unroll
    for (int itr = 0; itr < 2; itr++) {
        int idx = itr * 256 + tid;
        int r = idx >> 4, c4 = idx & 15;
        float4 val = *(const float4*)(x + (size_t)(row0 + r) * D_ + c4 * 4);
        *(float4*)&xs[r][c4 * 4] = val;
    }
    __syncthreads();
    int r = tid >> 3, m = tid & 7;
    float acc = 0.0f;
#pragma unroll
    for (int i = 0; i < 16; i++) {
        float4 a = *(const float4*)&xs[r][i * 4];
        float4 b = *(const float4*)&ps[m][i * 4];
        acc += a.x * b.x + a.y * b.y + a.z * b.z + a.w * b.w;
    }
    int grow = row0 + r;
    int b = grow / (L_ * H_);
    int l = (grow / H_) % L_;
    int h = grow % H_;
    o[(((size_t)(b * H_ + h) * L_ + l) << 3) + m] = fmaxf(RATIO * acc, 0.0f) + NUM_STAB;
}

// ============================================================
// Kernel 2: partial column sums of mask
// ============================================================
__global__ void __launch_bounds__(576) cmask_part_kernel(const float* __restrict__ mask) {
    int j  = threadIdx.x;
    int h  = blockIdx.y, ch = blockIdx.x;
    const float* mp = mask + ((size_t)h * L_ + ch * 72) * L_ + j;
    float s = 0.0f;
#pragma unroll 8
    for (int i = 0; i < 72; i++) s += mp[(size_t)i * L_];
    g_cmp[(ch * H_ + h) * L_ + j] = s;
}

// ============================================================
// Kernel 3: ks_sum
// ============================================================
__global__ void __launch_bounds__(64) ks_kernel() {
    int bh = blockIdx.x;
    int h  = bh % H_;
    int tid = threadIdx.x;
    __shared__ float red[64][8];
    float acc[8];
#pragma unroll
    for (int m = 0; m < 8; m++) acc[m] = 0.0f;
    for (int j = tid; j < L_; j += 64) {
        float c = 0.0f;
#pragma unroll
        for (int ch = 0; ch < 8; ch++) c += g_cmp[(ch * H_ + h) * L_ + j];
        const float4* kr = (const float4*)(g_kp + ((size_t)bh * L_ + j) * 8);
        float4 a = kr[0], bb = kr[1];
        acc[0] += c * a.x;  acc[1] += c * a.y;
        acc[2] += c * a.z;  acc[3] += c * a.w;
        acc[4] += c * bb.x; acc[5] += c * bb.y;
        acc[6] += c * bb.z; acc[7] += c * bb.w;
    }
#pragma unroll
    for (int m = 0; m < 8; m++) red[tid][m] = acc[m];
    __syncthreads();
    if (tid < 8) {
        float s = 0.0f;
        for (int i = 0; i < 64; i++) s += red[i][tid];
        g_ks[bh * 8 + tid] = s;
    }
}

// ============================================================
// Kernel 4: fused masked linear attention with HMMA (mma.sync bf16).
// grid (9, H, B), 128 threads (4 warps). i-tile 64, j-tiles of 64.
// Per jt: V tile -> smem bf16 hi/lo [j][d]; S-phase -> A bf16 hi/lo [i][j];
// warps compute 32i x 32d each: D += Ah*Vh + Al*Vh + Ah*Vl (fp32 regs).
// ============================================================
__global__ void __launch_bounds__(128)
attn_kernel(const float* __restrict__ v,
            const float* __restrict__ mask,
            float* __restrict__ out) {
    __shared__ __nv_bfloat16 Ah[64 * PAD], Al[64 * PAD];
    __shared__ __nv_bfloat16 Vh[64 * PAD], Vl[64 * PAD];
    __shared__ float Qs[64 * 8];
    __shared__ float KS[8];

    const int it = blockIdx.x, h = blockIdx.y, b = blockIdx.z;
    const int i0 = it * 64;
    const int bh = b * H_ + h;
    const int tid = threadIdx.x;
    const int wid = tid >> 5, lane = tid & 31;

    // stage Q' tile (64 rows x 8 = 128 float4) + ks_sum
    ((float4*)Qs)[tid] = ((const float4*)(g_qp + ((size_t)bh * L_ + i0) * 8))[tid];
    if (tid < 8) KS[tid] = g_ks[bh * 8 + tid];
    __syncthreads();

    float acc[2][4][4];
#pragma unroll
    for (int a = 0; a < 2; a++)
#pragma unroll
        for (int n = 0; n < 4; n++)
#pragma unroll
            for (int c = 0; c < 4; c++) acc[a][n][c] = 0.0f;

    const int sj = tid & 63, ihh = tid >> 6;
    const float* vbase = v + ((size_t)b * L_ * H_ + h) * D_;
    const float* maskc = mask + (size_t)h * L_ * L_ + (size_t)(i0 + ihh * 32) * L_ + sj;

    const uint32_t ah_b = (uint32_t)__cvta_generic_to_shared(Ah);
    const uint32_t al_b = (uint32_t)__cvta_generic_to_shared(Al);
    const uint32_t vh_b = (uint32_t)__cvta_generic_to_shared(Vh);
    const uint32_t vl_b = (uint32_t)__cvta_generic_to_shared(Vl);

    // per-lane ldmatrix address components
    const int lq = lane >> 3, lr = lane & 7;
    const int a_row_off = lr + ((lq & 1) << 3);   // + i_base
    const int a_col_off = (lq & 2) << 2;          // + k0
    const int b_row_off = ((lq & 1) << 3) + lr;   // + k0

    const int mi = (wid & 1) * 32, nw = (wid >> 1) * 32;

    for (int jt = 0; jt < 9; jt++) {
        const int j0 = jt * 64;
        if (jt) __syncthreads();

        // ---- stage V tile: fp32 -> bf16 hi/lo, rows [j][d], coalesced ----
#pragma unroll
        for (int iter = 0; iter < 8; iter++) {
            int idx = iter * 128 + tid;
            int r = idx >> 4, c4 = idx & 15;
            float4 vv = __ldg((const float4*)(vbase + (size_t)(j0 + r) * (H_ * D_) + c4 * 4));
            float f[4] = {vv.x, vv.y, vv.z, vv.w};
            __nv_bfloat16 hi0 = __float2bfloat16_rn(f[0]);
            __nv_bfloat16 hi1 = __float2bfloat16_rn(f[1]);
            __nv_bfloat16 hi2 = __float2bfloat16_rn(f[2]);
            __nv_bfloat16 hi3 = __float2bfloat16_rn(f[3]);
            __nv_bfloat162 ph01, ph23, pl01, pl23;
            ph01.x = hi0; ph01.y = hi1; ph23.x = hi2; ph23.y = hi3;
            pl01.x = __float2bfloat16_rn(f[0] - __bfloat162float(hi0));
            pl01.y = __float2bfloat16_rn(f[1] - __bfloat162float(hi1));
            pl23.x = __float2bfloat16_rn(f[2] - __bfloat162float(hi2));
            pl23.y = __float2bfloat16_rn(f[3] - __bfloat162float(hi3));
            uint2 wh = make_uint2(*(uint32_t*)&ph01, *(uint32_t*)&ph23);
            uint2 wl = make_uint2(*(uint32_t*)&pl01, *(uint32_t*)&pl23);
            *(uint2*)&Vh[r * PAD + c4 * 4] = wh;
            *(uint2*)&Vl[r * PAD + c4 * 4] = wl;
        }

        // ---- S phase: thread owns column j0+sj, 32 i's; A = mask*(q'.k') ----
        {
            const float* kp = g_kp + ((size_t)bh * L_ + j0 + sj) * 8;
            ulonglong2 kA = *(const ulonglong2*)kp;
            ulonglong2 kB = *(const ulonglong2*)(kp + 4);
#pragma unroll 4
            for (int ib = 0; ib < 32; ib++) {
                int i = ihh * 32 + ib;
                float mv = __ldg(maskc + (size_t)(jt * 64) /*j shift*/ - sj + sj + (size_t)ib * L_ + (j0 - jt * 64));
                // (simplifies to maskc + ib*L + j0; written plainly below)
                mv = __ldg(maskc + (size_t)ib * L_ + j0);
                const ulonglong2* qr = (const ulonglong2*)(Qs + i * 8);
                ulonglong2 qA = qr[0], qB = qr[1];
                ull s2 = mul2(qA.x, kA.x);
                ffma2(s2, qA.y, kA.y);
                ffma2(s2, qB.x, kB.x);
                ffma2(s2, qB.y, kB.y);
                float2 p = unpack2(s2);
                float a = (p.x + p.y) * mv;
                __nv_bfloat16 hi = __float2bfloat16_rn(a);
                Ah[i * PAD + sj] = hi;
                Al[i * PAD + sj] = __float2bfloat16_rn(a - __bfloat162float(hi));
            }
        }
        __syncthreads();

        // ---- HMMA phase: warp tile 32i x 32d ----
#pragma unroll
        for (int kk = 0; kk < 4; kk++) {
            const int k0 = kk * 16;
            uint32_t ah0[4], ah1[4], al0[4], al1[4];
            {
                uint32_t a0 = ah_b + ((mi + a_row_off) * PAD + k0 + a_col_off) * 2;
                uint32_t a1 = ah_b + ((mi + 16 + a_row_off) * PAD + k0 + a_col_off) * 2;
                uint32_t b0 = al_b + ((mi + a_row_off) * PAD + k0 + a_col_off) * 2;
                uint32_t b1 = al_b + ((mi + 16 + a_row_off) * PAD + k0 + a_col_off) * 2;
                ldmx4(a0, ah0); ldmx4(a1, ah1);
                ldmx4(b0, al0); ldmx4(b1, al1);
            }
#pragma unroll
            for (int nt = 0; nt < 4; nt++) {
                const int n0 = nw + nt * 8;
                uint32_t vh2[2], vl2[2];
                ldmx2t(vh_b + ((k0 + b_row_off) * PAD + n0) * 2, vh2);
                ldmx2t(vl_b + ((k0 + b_row_off) * PAD + n0) * 2, vl2);
                mma16816(acc[0][nt], ah0, vh2);
                mma16816(acc[0][nt], al0, vh2);
                mma16816(acc[0][nt], ah0, vl2);
                mma16816(acc[1][nt], ah1, vh2);
                mma16816(acc[1][nt], al1, vh2);
                mma16816(acc[1][nt], ah1, vl2);
            }
        }
    }

    // ---- epilogue: normalizer + store ----
    float rn[2][2];
#pragma unroll
    for (int isub = 0; isub < 2; isub++)
#pragma unroll
        for (int half = 0; half < 2; half++) {
            int row = mi + isub * 16 + (lane >> 2) + half * 8;
            float n = 0.0f;
#pragma unroll
            for (int m = 0; m < 8; m++) n += Qs[row * 8 + m] * KS[m];
            rn[isub][half] = 1.0f / n;
        }

#pragma unroll
    for (int isub = 0; isub < 2; isub++) {
        int r0 = mi + isub * 16 + (lane >> 2);
#pragma unroll
        for (int nt = 0; nt < 4; nt++) {
            int col = nw + nt * 8 + 2 * (lane & 3);
            float* o0 = out + (((size_t)b * L_ + i0 + r0) * H_ + h) * D_ + col;
            float* o1 = out + (((size_t)b * L_ + i0 + r0 + 8) * H_ + h) * D_ + col;
            *(float2*)o0 = make_float2(acc[isub][nt][0] * rn[isub][0],
                                       acc[isub][nt][1] * rn[isub][0]);
            *(float2*)o1 = make_float2(acc[isub][nt][2] * rn[isub][1],
                                       acc[isub][nt][3] * rn[isub][1]);
        }
    }
}

// ============================================================
extern "C" void kernel_launch(void* const* d_in, const int* in_sizes, int n_in,
                              void* d_out, int out_size) {
    const float* q    = (const float*)d_in[0];
    const float* k    = (const float*)d_in[1];
    const float* v    = (const float*)d_in[2];
    const float* proj = (const float*)d_in[3];
    const float* mask = (const float*)d_in[4];
    float* out = (float*)d_out;

    {
        dim3 grid(B_ * L_ * H_ / 32, 2);
        feat_kernel<<<grid, 256>>>(q, k, proj);
    }
    {
        dim3 grid(8, H_);
        cmask_part_kernel<<<grid, 576>>>(mask);
    }
    ks_kernel<<<B_ * H_, 64>>>();
    {
        dim3 grid(9, H_, B_);
        attn_kernel<<<grid, 128>>>(v, mask, out);
    }
}

// round 7
// speedup vs baseline: 3.0704x; 1.1286x over previous
#include <cuda_runtime.h>
#include <cuda_bf16.h>
#include <cstdint>

#define B_ 16
#define L_ 576
#define H_ 12
#define D_ 64
#define M_ 8
#define NUM_STAB 1e-3f
#define RATIO 0.35355339059327373f   /* 1/sqrt(M) */

// -------- scratch (device globals: no allocation allowed) --------
__device__ float g_qp[B_ * H_ * L_ * M_];   // q' fp32 [bh][l][8] (normalizer)
__device__ float g_kp[B_ * H_ * L_ * M_];   // k' fp32 [bh][l][8] (ks_sum)
__device__ float g_cmp[8 * H_ * L_];
__device__ float g_ks[B_ * H_ * M_];
// packed split-bf16 operands
__device__ __align__(16) __nv_bfloat16 g_qe[B_ * H_ * L_ * 32];  // [bh][l][32]=[qhi,qhi,qlo,0]
__device__ __align__(16) __nv_bfloat16 g_kt[B_ * H_ * 32 * L_];  // [bh][k=32][l]=[khi,klo,khi,0]
__device__ __align__(16) __nv_bfloat16 g_vh[B_ * H_ * L_ * 64];  // [bh][l][64]
__device__ __align__(16) __nv_bfloat16 g_vl[B_ * H_ * L_ * 64];

// -------- helpers --------
__device__ __forceinline__ void ldmx4(uint32_t addr, uint32_t* r) {
    asm volatile("ldmatrix.sync.aligned.m8n8.x4.shared.b16 {%0,%1,%2,%3}, [%4];"
                 : "=r"(r[0]), "=r"(r[1]), "=r"(r[2]), "=r"(r[3]) : "r"(addr));
}
__device__ __forceinline__ void ldmx2t(uint32_t addr, uint32_t* r) {
    asm volatile("ldmatrix.sync.aligned.m8n8.x2.trans.shared.b16 {%0,%1}, [%2];"
                 : "=r"(r[0]), "=r"(r[1]) : "r"(addr));
}
__device__ __forceinline__ void mma16816(float* c, const uint32_t* a, const uint32_t* b) {
    asm volatile("mma.sync.aligned.m16n8k16.row.col.f32.bf16.bf16.f32 "
                 "{%0,%1,%2,%3}, {%4,%5,%6,%7}, {%8,%9}, {%0,%1,%2,%3};"
                 : "+f"(c[0]), "+f"(c[1]), "+f"(c[2]), "+f"(c[3])
                 : "r"(a[0]), "r"(a[1]), "r"(a[2]), "r"(a[3]), "r"(b[0]), "r"(b[1]));
}
__device__ __forceinline__ uint32_t cvtbf2(float hi, float lo) {
    uint32_t r; asm("cvt.rn.bf16x2.f32 %0, %1, %2;" : "=r"(r) : "f"(hi), "f"(lo)); return r;
}
__device__ __forceinline__ unsigned short f2bf(float x) {
    unsigned short u; asm("cvt.rn.bf16.f32 %0, %1;" : "=h"(u) : "f"(x)); return u;
}
__device__ __forceinline__ uint32_t smem_u32(const void* p) {
    return (uint32_t)__cvta_generic_to_shared(p);
}

// ============================================================
// Kernel 1: ReLU random features -> g_qp / g_kp fp32 (proven r4)
// ============================================================
__global__ void __launch_bounds__(256) feat_kernel(const float* __restrict__ q,
                                                   const float* __restrict__ k,
                                                   const float* __restrict__ proj) {
    __shared__ float xs[32][68];
    __shared__ float ps[8][68];
    int tid = threadIdx.x;
    const float* x = blockIdx.y ? k : q;
    float* o       = blockIdx.y ? g_kp : g_qp;
    {
        float2 pv = ((const float2*)proj)[tid];
        ps[tid >> 5][(tid & 31) * 2]     = pv.x;
        ps[tid >> 5][(tid & 31) * 2 + 1] = pv.y;
    }
    int row0 = blockIdx.x * 32;
#pragma unroll
    for (int itr = 0; itr < 2; itr++) {
        int idx = itr * 256 + tid;
        int r = idx >> 4, c4 = idx & 15;
        float4 val = *(const float4*)(x + (size_t)(row0 + r) * D_ + c4 * 4);
        *(float4*)&xs[r][c4 * 4] = val;
    }
    __syncthreads();
    int r = tid >> 3, m = tid & 7;
    float acc = 0.0f;
#pragma unroll
    for (int i = 0; i < 16; i++) {
        float4 a = *(const float4*)&xs[r][i * 4];
        float4 b = *(const float4*)&ps[m][i * 4];
        acc += a.x * b.x + a.y * b.y + a.z * b.z + a.w * b.w;
    }
    int grow = row0 + r;
    int b = grow / (L_ * H_);
    int l = (grow / H_) % L_;
    int h = grow % H_;
    o[(((size_t)(b * H_ + h) * L_ + l) << 3) + m] = fmaxf(RATIO * acc, 0.0f) + NUM_STAB;
}

// ============================================================
// Kernel 1b: build packed split-bf16 operands Qe, KtT, Vh, Vl
// grid (9, H, B), 128 threads; chunk = 64 l's
// ============================================================
__global__ void __launch_bounds__(128) conv_kernel(const float* __restrict__ v) {
    __shared__ unsigned short kt[32][64];
    const int ch = blockIdx.x, h = blockIdx.y, b = blockIdx.z;
    const int bh = b * H_ + h, l0 = ch * 64;
    const int tid = threadIdx.x;
    const int r = tid >> 1, hf = tid & 1;

    // ---- Q ext: [qhi(8) qhi(8) qlo(8) 0(8)] ----
    {
        const float4 qv = *(const float4*)(g_qp + ((size_t)bh * L_ + l0 + r) * 8 + hf * 4);
        float f[4] = {qv.x, qv.y, qv.z, qv.w};
        uint32_t hi2[2], lo2[2];
#pragma unroll
        for (int e = 0; e < 2; e++) {
            uint32_t c0 = __float_as_uint(f[2 * e]), c1 = __float_as_uint(f[2 * e + 1]);
            hi2[e] = __byte_perm(c0, c1, 0x7632);
            float lo0 = f[2 * e]     - __uint_as_float(c0 & 0xFFFF0000u);
            float lo1 = f[2 * e + 1] - __uint_as_float(c1 & 0xFFFF0000u);
            lo2[e] = cvtbf2(lo1, lo0);
        }
        __nv_bfloat16* qr = g_qe + ((size_t)bh * L_ + l0 + r) * 32;
        *(uint2*)(qr + hf * 4)      = make_uint2(hi2[0], hi2[1]);
        *(uint2*)(qr + 8 + hf * 4)  = make_uint2(hi2[0], hi2[1]);
        *(uint2*)(qr + 16 + hf * 4) = make_uint2(lo2[0], lo2[1]);
        *(uint2*)(qr + 24 + hf * 4) = make_uint2(0u, 0u);
    }
    // ---- K ext -> smem transpose: rows [khi(8) klo(8) khi(8) 0(8)] ----
    {
        const float4 kv = *(const float4*)(g_kp + ((size_t)bh * L_ + l0 + r) * 8 + hf * 4);
        float f[4] = {kv.x, kv.y, kv.z, kv.w};
#pragma unroll
        for (int e = 0; e < 4; e++) {
            uint32_t ci = __float_as_uint(f[e]);
            unsigned short hs = (unsigned short)(ci >> 16);
            unsigned short ls = f2bf(f[e] - __uint_as_float(ci & 0xFFFF0000u));
            int k = hf * 4 + e;
            kt[k][r]      = hs;
            kt[k + 8][r]  = ls;
            kt[k + 16][r] = hs;
            kt[k + 24][r] = 0;
        }
    }
    __syncthreads();
    // write KtT rows coalesced (128B per row)
    {
        int k = tid >> 2, c = (tid & 3) * 16;
        const uint4* src = (const uint4*)&kt[k][c];
        __nv_bfloat16* dst = g_kt + ((size_t)bh * 32 + k) * L_ + l0 + c;
        *(uint4*)dst       = src[0];
        *(uint4*)(dst + 8) = src[1];
    }
    // ---- V hi/lo ----
#pragma unroll
    for (int iter = 0; iter < 8; iter++) {
        int idx = iter * 128 + tid;
        int rr = idx >> 4, c4 = idx & 15;
        const float4 vv = __ldg((const float4*)(v + (((size_t)b * L_ + l0 + rr) * H_ + h) * D_ + c4 * 4));
        float f[4] = {vv.x, vv.y, vv.z, vv.w};
        uint32_t u0 = __float_as_uint(f[0]), u1 = __float_as_uint(f[1]);
        uint32_t u2 = __float_as_uint(f[2]), u3 = __float_as_uint(f[3]);
        uint32_t h01 = __byte_perm(u0, u1, 0x7632);
        uint32_t h23 = __byte_perm(u2, u3, 0x7632);
        float l0f = f[0] - __uint_as_float(u0 & 0xFFFF0000u);
        float l1f = f[1] - __uint_as_float(u1 & 0xFFFF0000u);
        float l2f = f[2] - __uint_as_float(u2 & 0xFFFF0000u);
        float l3f = f[3] - __uint_as_float(u3 & 0xFFFF0000u);
        size_t o = ((size_t)bh * L_ + l0 + rr) * 64 + c4 * 4;
        *(uint2*)(g_vh + o) = make_uint2(h01, h23);
        *(uint2*)(g_vl + o) = make_uint2(cvtbf2(l1f, l0f), cvtbf2(l3f, l2f));
    }
}

// ============================================================
// Kernel 2: partial column sums of mask
// ============================================================
__global__ void __launch_bounds__(576) cmask_part_kernel(const float* __restrict__ mask) {
    int j  = threadIdx.x;
    int h  = blockIdx.y, ch = blockIdx.x;
    const float* mp = mask + ((size_t)h * L_ + ch * 72) * L_ + j;
    float s = 0.0f;
#pragma unroll 8
    for (int i = 0; i < 72; i++) s += mp[(size_t)i * L_];
    g_cmp[(ch * H_ + h) * L_ + j] = s;
}

// ============================================================
// Kernel 3: ks_sum
// ============================================================
__global__ void __launch_bounds__(64) ks_kernel() {
    int bh = blockIdx.x;
    int h  = bh % H_;
    int tid = threadIdx.x;
    __shared__ float red[64][8];
    float acc[8];
#pragma unroll
    for (int m = 0; m < 8; m++) acc[m] = 0.0f;
    for (int j = tid; j < L_; j += 64) {
        float c = 0.0f;
#pragma unroll
        for (int ch = 0; ch < 8; ch++) c += g_cmp[(ch * H_ + h) * L_ + j];
        const float4* kr = (const float4*)(g_kp + ((size_t)bh * L_ + j) * 8);
        float4 a = kr[0], bb = kr[1];
        acc[0] += c * a.x;  acc[1] += c * a.y;
        acc[2] += c * a.z;  acc[3] += c * a.w;
        acc[4] += c * bb.x; acc[5] += c * bb.y;
        acc[6] += c * bb.z; acc[7] += c * bb.w;
    }
#pragma unroll
    for (int m = 0; m < 8; m++) red[tid][m] = acc[m];
    __syncthreads();
    if (tid < 8) {
        float s = 0.0f;
        for (int i = 0; i < 64; i++) s += red[i][tid];
        g_ks[bh * 8 + tid] = s;
    }
}

// ============================================================
// Kernel 4: fused attention, all-tensor-core, A stays in registers.
// grid (9, H, B), 128 thr / 4 warps; warp = 16 i-rows x 64 j/d cols.
// ============================================================
__global__ void __launch_bounds__(128)
attn_kernel(const float* __restrict__ mask, float* __restrict__ out) {
    __shared__ __nv_bfloat16 Vh[64][72], Vl[64][72], Kt[32][72];
    __shared__ __nv_bfloat16 Qe[64][40];
    __shared__ float Qs[64][8];
    __shared__ float KS[8];

    const int it = blockIdx.x, h = blockIdx.y, b = blockIdx.z;
    const int i0 = it * 64, bh = b * H_ + h;
    const int tid = threadIdx.x, wid = tid >> 5, lane = tid & 31;
    const int mi = wid * 16;

    // stage Qs fp32 + KS + Qe
    ((float4*)Qs)[tid] = ((const float4*)(g_qp + ((size_t)bh * L_ + i0) * 8))[tid];
    if (tid < 8) KS[tid] = g_ks[bh * 8 + tid];
#pragma unroll
    for (int iter = 0; iter < 2; iter++) {
        int idx = iter * 128 + tid;
        int r = idx >> 2, c = (idx & 3) * 8;
        *(uint4*)&Qe[r][c] = __ldg((const uint4*)(g_qe + ((size_t)bh * L_ + i0 + r) * 32 + c));
    }
    __syncthreads();

    const int lq = lane >> 3, lr = lane & 7;
    const int a_row = lr + ((lq & 1) << 3);
    const int a_col = (lq & 2) << 2;
    const int b_row = ((lq & 1) << 3) + lr;

    const uint32_t qe_b = smem_u32(Qe);
    const uint32_t vh_b = smem_u32(Vh);
    const uint32_t vl_b = smem_u32(Vl);
    const uint32_t kt_b = smem_u32(Kt);

    // Q fragments (jt-invariant): 2 k16 chunks
    uint32_t qf[2][4];
    ldmx4(qe_b + ((mi + a_row) * 40 + a_col) * 2, qf[0]);
    ldmx4(qe_b + ((mi + a_row) * 40 + 16 + a_col) * 2, qf[1]);

    float accv[8][4];
#pragma unroll
    for (int n = 0; n < 8; n++)
#pragma unroll
        for (int c = 0; c < 4; c++) accv[n][c] = 0.0f;

    const float* maskh = mask + (size_t)h * L_ * L_;
    const int r0g = i0 + mi + (lane >> 2);

    for (int jt = 0; jt < 9; jt++) {
        const int j0 = jt * 64;
        __syncthreads();
        // ---- stage V hi/lo (pure 16B copies) ----
#pragma unroll
        for (int iter = 0; iter < 4; iter++) {
            int idx = iter * 128 + tid;
            int r = idx >> 3, c = (idx & 7) * 8;
            size_t o = ((size_t)bh * L_ + j0 + r) * 64 + c;
            *(uint4*)&Vh[r][c] = __ldg((const uint4*)(g_vh + o));
            *(uint4*)&Vl[r][c] = __ldg((const uint4*)(g_vl + o));
        }
        // ---- stage Kt ----
#pragma unroll
        for (int iter = 0; iter < 2; iter++) {
            int idx = iter * 128 + tid;
            int r = idx >> 3, c = (idx & 7) * 8;
            *(uint4*)&Kt[r][c] = __ldg((const uint4*)(g_kt + ((size_t)bh * 32 + r) * L_ + j0 + c));
        }
        __syncthreads();

        // ---- S via HMMA: 8 n-frags x 2 chunks ----
        float sc[8][4];
#pragma unroll
        for (int nt = 0; nt < 8; nt++) {
            uint32_t kb0[2], kb1[2];
            ldmx2t(kt_b + (b_row * 72 + nt * 8) * 2, kb0);
            ldmx2t(kt_b + ((16 + b_row) * 72 + nt * 8) * 2, kb1);
            sc[nt][0] = sc[nt][1] = sc[nt][2] = sc[nt][3] = 0.0f;
            mma16816(sc[nt], qf[0], kb0);
            mma16816(sc[nt], qf[1], kb1);
        }
        // ---- mask multiply (fp32) + truncation split pack into A-frags ----
        uint32_t ah[4][4], al[4][4];
#pragma unroll
        for (int nt = 0; nt < 8; nt++) {
            const float* mp = maskh + (size_t)r0g * L_ + j0 + nt * 8 + 2 * (lane & 3);
            float2 m0 = __ldg((const float2*)mp);
            float2 m1 = __ldg((const float2*)(mp + 8 * (size_t)L_));
            float c0 = sc[nt][0] * m0.x, c1 = sc[nt][1] * m0.y;
            float c2 = sc[nt][2] * m1.x, c3 = sc[nt][3] * m1.y;
            uint32_t u0 = __float_as_uint(c0), u1 = __float_as_uint(c1);
            uint32_t u2 = __float_as_uint(c2), u3 = __float_as_uint(c3);
            int ki = nt >> 1, ps = (nt & 1) * 2;
            ah[ki][ps]     = __byte_perm(u0, u1, 0x7632);
            ah[ki][ps + 1] = __byte_perm(u2, u3, 0x7632);
            float l0 = c0 - __uint_as_float(u0 & 0xFFFF0000u);
            float l1 = c1 - __uint_as_float(u1 & 0xFFFF0000u);
            float l2 = c2 - __uint_as_float(u2 & 0xFFFF0000u);
            float l3 = c3 - __uint_as_float(u3 & 0xFFFF0000u);
            al[ki][ps]     = cvtbf2(l1, l0);
            al[ki][ps + 1] = cvtbf2(l3, l2);
        }
        // ---- AV: D += Ah*Vh + Al*Vh + Ah*Vl ----
#pragma unroll
        for (int ki = 0; ki < 4; ki++) {
#pragma unroll
            for (int nt = 0; nt < 8; nt++) {
                uint32_t vh2[2], vl2[2];
                ldmx2t(vh_b + ((ki * 16 + b_row) * 72 + nt * 8) * 2, vh2);
                ldmx2t(vl_b + ((ki * 16 + b_row) * 72 + nt * 8) * 2, vl2);
                mma16816(accv[nt], ah[ki], vh2);
                mma16816(accv[nt], al[ki], vh2);
                mma16816(accv[nt], ah[ki], vl2);
            }
        }
    }

    // ---- epilogue: normalizer + store ----
    const int rl = mi + (lane >> 2);
    float n0 = 0.0f, n1 = 0.0f;
#pragma unroll
    for (int m = 0; m < 8; m++) {
        n0 += Qs[rl][m] * KS[m];
        n1 += Qs[rl + 8][m] * KS[m];
    }
    float rn0 = 1.0f / n0, rn1 = 1.0f / n1;
#pragma unroll
    for (int nt = 0; nt < 8; nt++) {
        float* o0 = out + (((size_t)b * L_ + i0 + rl) * H_ + h) * D_ + nt * 8 + 2 * (lane & 3);
        float* o1 = o0 + (size_t)8 * (H_ * D_);
        *(float2*)o0 = make_float2(accv[nt][0] * rn0, accv[nt][1] * rn0);
        *(float2*)o1 = make_float2(accv[nt][2] * rn1, accv[nt][3] * rn1);
    }
}

// ============================================================
extern "C" void kernel_launch(void* const* d_in, const int* in_sizes, int n_in,
                              void* d_out, int out_size) {
    const float* q    = (const float*)d_in[0];
    const float* k    = (const float*)d_in[1];
    const float* v    = (const float*)d_in[2];
    const float* proj = (const float*)d_in[3];
    const float* mask = (const float*)d_in[4];
    float* out = (float*)d_out;

    {
        dim3 grid(B_ * L_ * H_ / 32, 2);
        feat_kernel<<<grid, 256>>>(q, k, proj);
    }
    {
        dim3 grid(9, H_, B_);
        conv_kernel<<<grid, 128>>>(v);
    }
    {
        dim3 grid(8, H_);
        cmask_part_kernel<<<grid, 576>>>(mask);
    }
    ks_kernel<<<B_ * H_, 64>>>();
    {
        dim3 grid(9, H_, B_);
        attn_kernel<<<grid, 128>>>(mask, out);
    }
}

// round 9
// speedup vs baseline: 3.5732x; 1.1638x over previous
#include <cuda_runtime.h>
#include <cuda_bf16.h>
#include <cstdint>

#define B_ 16
#define L_ 576
#define H_ 12
#define D_ 64
#define M_ 8
#define NUM_STAB 1e-3f
#define RATIO 0.35355339059327373f   /* 1/sqrt(M) */

// -------- scratch (device globals: no allocation allowed) --------
__device__ float g_qp[B_ * H_ * L_ * M_];           // q' fp32 [bh][l][8] (normalizer)
__device__ float g_cmp[8 * H_ * L_];                // mask column-sum partials
__device__ float g_ksp[B_ * H_ * 9 * M_];           // ks partials [bh][ch][8]
__device__ __align__(16) __nv_bfloat16 g_qe[B_ * H_ * L_ * 32];  // [bh][l][32]=[qhi,qhi,qlo,0]
__device__ __align__(16) __nv_bfloat16 g_kt[B_ * H_ * 32 * L_];  // [bh][k=32][l]=[khi,klo,khi,0]
__device__ __align__(16) __nv_bfloat16 g_vh[B_ * H_ * L_ * 64];  // [bh][l][64]
__device__ __align__(16) __nv_bfloat16 g_vl[B_ * H_ * L_ * 64];

// -------- helpers --------
__device__ __forceinline__ void ldmx4(uint32_t addr, uint32_t* r) {
    asm volatile("ldmatrix.sync.aligned.m8n8.x4.shared.b16 {%0,%1,%2,%3}, [%4];"
                 : "=r"(r[0]), "=r"(r[1]), "=r"(r[2]), "=r"(r[3]) : "r"(addr));
}
__device__ __forceinline__ void ldmx2t(uint32_t addr, uint32_t* r) {
    asm volatile("ldmatrix.sync.aligned.m8n8.x2.trans.shared.b16 {%0,%1}, [%2];"
                 : "=r"(r[0]), "=r"(r[1]) : "r"(addr));
}
__device__ __forceinline__ void mma16816(float* c, const uint32_t* a, const uint32_t* b) {
    asm volatile("mma.sync.aligned.m16n8k16.row.col.f32.bf16.bf16.f32 "
                 "{%0,%1,%2,%3}, {%4,%5,%6,%7}, {%8,%9}, {%0,%1,%2,%3};"
                 : "+f"(c[0]), "+f"(c[1]), "+f"(c[2]), "+f"(c[3])
                 : "r"(a[0]), "r"(a[1]), "r"(a[2]), "r"(a[3]), "r"(b[0]), "r"(b[1]));
}
__device__ __forceinline__ uint32_t cvtbf2(float hi, float lo) {
    uint32_t r; asm("cvt.rn.bf16x2.f32 %0, %1, %2;" : "=r"(r) : "f"(hi), "f"(lo)); return r;
}
__device__ __forceinline__ unsigned short f2bf(float x) {
    unsigned short u; asm("cvt.rn.bf16.f32 %0, %1;" : "=h"(u) : "f"(x)); return u;
}
__device__ __forceinline__ uint32_t smem_u32(const void* p) {
    return (uint32_t)__cvta_generic_to_shared(p);
}

// ============================================================
// Kernel 1: partial column sums of mask (unchanged, warms L2 too)
// ============================================================
__global__ void __launch_bounds__(576) cmask_part_kernel(const float* __restrict__ mask) {
    int j  = threadIdx.x;
    int h  = blockIdx.y, ch = blockIdx.x;
    const float* mp = mask + ((size_t)h * L_ + ch * 72) * L_ + j;
    float s = 0.0f;
#pragma unroll 8
    for (int i = 0; i < 72; i++) s += mp[(size_t)i * L_];
    g_cmp[(ch * H_ + h) * L_ + j] = s;
}

// ============================================================
// Kernel 2: fused prep. grid (9 chunks, H, B), 128 threads.
// Per (b,h,64 l's): ReLU features for q,k; emits g_qp, Qe packed,
// Kt transposed, Vh/Vl split, and the ks partial for this chunk.
// ============================================================
__global__ void __launch_bounds__(128) prep_kernel(const float* __restrict__ q,
                                                   const float* __restrict__ k,
                                                   const float* __restrict__ v,
                                                   const float* __restrict__ proj) {
    __shared__ float ps[8][68];
    __shared__ float xs[64][68];
    __shared__ unsigned short kt[32][64];
    __shared__ float red[64][8];
    __shared__ float cm[64];

    const int ch = blockIdx.x, h = blockIdx.y, b = blockIdx.z;
    const int bh = b * H_ + h, l0 = ch * 64;
    const int tid = threadIdx.x;
    const int r = tid >> 1, hf = tid & 1;

    // proj -> smem (512 floats, 128 thr x float4)
    {
        float4 pv = ((const float4*)proj)[tid];
        ps[tid >> 4][(tid & 15) * 4 + 0] = pv.x;
        ps[tid >> 4][(tid & 15) * 4 + 1] = pv.y;
        ps[tid >> 4][(tid & 15) * 4 + 2] = pv.z;
        ps[tid >> 4][(tid & 15) * 4 + 3] = pv.w;
    }
    // cmask row sums for this chunk's j's
    if (tid < 64) {
        float s = 0.0f;
#pragma unroll
        for (int c2 = 0; c2 < 8; c2++) s += g_cmp[(c2 * H_ + h) * L_ + l0 + tid];
        cm[tid] = s;
    }

    // ---------- Q ----------
#pragma unroll
    for (int iter = 0; iter < 8; iter++) {
        int idx = iter * 128 + tid;
        int rr = idx >> 4, c4 = idx & 15;
        float4 val = __ldg((const float4*)(q + (((size_t)b * L_ + l0 + rr) * H_ + h) * D_ + c4 * 4));
        *(float4*)&xs[rr][c4 * 4] = val;
    }
    __syncthreads();
    {
        float f[4];
#pragma unroll
        for (int e = 0; e < 4; e++) {
            int m = hf * 4 + e;
            float acc = 0.0f;
#pragma unroll
            for (int i = 0; i < 16; i++) {
                float4 a = *(const float4*)&xs[r][i * 4];
                float4 p = *(const float4*)&ps[m][i * 4];
                acc += a.x * p.x + a.y * p.y + a.z * p.z + a.w * p.w;
            }
            f[e] = fmaxf(RATIO * acc, 0.0f) + NUM_STAB;
        }
        // fp32 for normalizer
        *(float4*)(g_qp + ((size_t)bh * L_ + l0 + r) * 8 + hf * 4) = make_float4(f[0], f[1], f[2], f[3]);
        // packed Qe [qhi qhi qlo 0]
        uint32_t hi2[2], lo2[2];
#pragma unroll
        for (int e = 0; e < 2; e++) {
            uint32_t c0 = __float_as_uint(f[2 * e]), c1 = __float_as_uint(f[2 * e + 1]);
            hi2[e] = __byte_perm(c0, c1, 0x7632);
            float lo0 = f[2 * e]     - __uint_as_float(c0 & 0xFFFF0000u);
            float lo1 = f[2 * e + 1] - __uint_as_float(c1 & 0xFFFF0000u);
            lo2[e] = cvtbf2(lo1, lo0);
        }
        __nv_bfloat16* qr = g_qe + ((size_t)bh * L_ + l0 + r) * 32;
        *(uint2*)(qr + hf * 4)      = make_uint2(hi2[0], hi2[1]);
        *(uint2*)(qr + 8 + hf * 4)  = make_uint2(hi2[0], hi2[1]);
        *(uint2*)(qr + 16 + hf * 4) = make_uint2(lo2[0], lo2[1]);
        *(uint2*)(qr + 24 + hf * 4) = make_uint2(0u, 0u);
    }
    __syncthreads();

    // ---------- K ----------
#pragma unroll
    for (int iter = 0; iter < 8; iter++) {
        int idx = iter * 128 + tid;
        int rr = idx >> 4, c4 = idx & 15;
        float4 val = __ldg((const float4*)(k + (((size_t)b * L_ + l0 + rr) * H_ + h) * D_ + c4 * 4));
        *(float4*)&xs[rr][c4 * 4] = val;
    }
    __syncthreads();
    {
        float cmv = cm[r];
#pragma unroll
        for (int e = 0; e < 4; e++) {
            int m = hf * 4 + e;
            float acc = 0.0f;
#pragma unroll
            for (int i = 0; i < 16; i++) {
                float4 a = *(const float4*)&xs[r][i * 4];
                float4 p = *(const float4*)&ps[m][i * 4];
                acc += a.x * p.x + a.y * p.y + a.z * p.z + a.w * p.w;
            }
            float f = fmaxf(RATIO * acc, 0.0f) + NUM_STAB;
            uint32_t ci = __float_as_uint(f);
            unsigned short hs = (unsigned short)(ci >> 16);
            unsigned short ls = f2bf(f - __uint_as_float(ci & 0xFFFF0000u));
            int kk = hf * 4 + e;
            kt[kk][r]      = hs;
            kt[kk + 8][r]  = ls;
            kt[kk + 16][r] = hs;
            kt[kk + 24][r] = 0;
            red[r][m] = cmv * f;
        }
    }
    __syncthreads();
    // Kt rows -> gmem coalesced
    {
        int kk = tid >> 2, c = (tid & 3) * 16;
        const uint4* src = (const uint4*)&kt[kk][c];
        __nv_bfloat16* dst = g_kt + ((size_t)bh * 32 + kk) * L_ + l0 + c;
        *(uint4*)dst       = src[0];
        *(uint4*)(dst + 8) = src[1];
    }
    // ks partial
    if (tid < 8) {
        float s = 0.0f;
#pragma unroll 16
        for (int i = 0; i < 64; i++) s += red[i][tid];
        g_ksp[((size_t)bh * 9 + ch) * 8 + tid] = s;
    }

    // ---------- V ----------
#pragma unroll
    for (int iter = 0; iter < 8; iter++) {
        int idx = iter * 128 + tid;
        int rr = idx >> 4, c4 = idx & 15;
        const float4 vv = __ldg((const float4*)(v + (((size_t)b * L_ + l0 + rr) * H_ + h) * D_ + c4 * 4));
        float f[4] = {vv.x, vv.y, vv.z, vv.w};
        uint32_t u0 = __float_as_uint(f[0]), u1 = __float_as_uint(f[1]);
        uint32_t u2 = __float_as_uint(f[2]), u3 = __float_as_uint(f[3]);
        uint32_t h01 = __byte_perm(u0, u1, 0x7632);
        uint32_t h23 = __byte_perm(u2, u3, 0x7632);
        float l0f = f[0] - __uint_as_float(u0 & 0xFFFF0000u);
        float l1f = f[1] - __uint_as_float(u1 & 0xFFFF0000u);
        float l2f = f[2] - __uint_as_float(u2 & 0xFFFF0000u);
        float l3f = f[3] - __uint_as_float(u3 & 0xFFFF0000u);
        size_t o = ((size_t)bh * L_ + l0 + rr) * 64 + c4 * 4;
        *(uint2*)(g_vh + o) = make_uint2(h01, h23);
        *(uint2*)(g_vl + o) = make_uint2(cvtbf2(l1f, l0f), cvtbf2(l3f, l2f));
    }
}

// ============================================================
// Kernel 3: fused attention. grid (5, H, B), 256 thr / 8 warps.
// i-tile 128 (last CTA: 64 valid rows, clamped). Warp = 16 rows.
// ============================================================
__global__ void __launch_bounds__(256)
attn_kernel(const float* __restrict__ mask, float* __restrict__ out) {
    __shared__ __nv_bfloat16 Vh[64][72], Vl[64][72], Kt[32][72];
    __shared__ __nv_bfloat16 Qe[128][40];
    __shared__ float Qs[128][8];
    __shared__ float KS[8];

    const int it = blockIdx.x, h = blockIdx.y, b = blockIdx.z;
    const int i0 = it * 128, bh = b * H_ + h;
    const int tid = threadIdx.x, wid = tid >> 5, lane = tid & 31;
    const int mi = wid * 16;

    // stage Qs fp32 (clamped rows)
    {
        int rr = tid >> 1, part = tid & 1;
        int gi = min(i0 + rr, L_ - 1);
        ((float4*)&Qs[rr][0])[part] =
            *(const float4*)(g_qp + ((size_t)bh * L_ + gi) * 8 + part * 4);
    }
    if (tid < 8) {
        float s = 0.0f;
#pragma unroll
        for (int c2 = 0; c2 < 9; c2++) s += g_ksp[((size_t)bh * 9 + c2) * 8 + tid];
        KS[tid] = s;
    }
    // stage Qe (clamped)
#pragma unroll
    for (int iter = 0; iter < 2; iter++) {
        int idx = iter * 256 + tid;
        int rr = idx >> 2, c = (idx & 3) * 8;
        int gi = min(i0 + rr, L_ - 1);
        *(uint4*)&Qe[rr][c] = __ldg((const uint4*)(g_qe + ((size_t)bh * L_ + gi) * 32 + c));
    }
    __syncthreads();

    const int lq = lane >> 3, lr = lane & 7;
    const int a_row = lr + ((lq & 1) << 3);
    const int a_col = (lq & 2) << 2;
    const int b_row = ((lq & 1) << 3) + lr;

    const uint32_t qe_b = smem_u32(Qe);
    const uint32_t vh_b = smem_u32(Vh);
    const uint32_t vl_b = smem_u32(Vl);
    const uint32_t kt_b = smem_u32(Kt);

    uint32_t qf[2][4];
    ldmx4(qe_b + ((mi + a_row) * 40 + a_col) * 2, qf[0]);
    ldmx4(qe_b + ((mi + a_row) * 40 + 16 + a_col) * 2, qf[1]);

    float accv[8][4];
#pragma unroll
    for (int n = 0; n < 8; n++)
#pragma unroll
        for (int c = 0; c < 4; c++) accv[n][c] = 0.0f;

    const float* maskh = mask + (size_t)h * L_ * L_;
    const int r0c = min(i0 + mi + (lane >> 2), L_ - 1);
    const int r1c = min(i0 + mi + (lane >> 2) + 8, L_ - 1);

    for (int jt = 0; jt < 9; jt++) {
        const int j0 = jt * 64;
        __syncthreads();
        // stage V hi/lo (16B copies)
#pragma unroll
        for (int iter = 0; iter < 2; iter++) {
            int idx = iter * 256 + tid;
            int rr = idx >> 3, c = (idx & 7) * 8;
            size_t o = ((size_t)bh * L_ + j0 + rr) * 64 + c;
            *(uint4*)&Vh[rr][c] = __ldg((const uint4*)(g_vh + o));
            *(uint4*)&Vl[rr][c] = __ldg((const uint4*)(g_vl + o));
        }
        // stage Kt (exactly 256 x uint4)
        {
            int rr = tid >> 3, c = (tid & 7) * 8;
            *(uint4*)&Kt[rr][c] = __ldg((const uint4*)(g_kt + ((size_t)bh * 32 + rr) * L_ + j0 + c));
        }
        __syncthreads();

        // S via HMMA
        float sc[8][4];
#pragma unroll
        for (int nt = 0; nt < 8; nt++) {
            uint32_t kb0[2], kb1[2];
            ldmx2t(kt_b + (b_row * 72 + nt * 8) * 2, kb0);
            ldmx2t(kt_b + ((16 + b_row) * 72 + nt * 8) * 2, kb1);
            sc[nt][0] = sc[nt][1] = sc[nt][2] = sc[nt][3] = 0.0f;
            mma16816(sc[nt], qf[0], kb0);
            mma16816(sc[nt], qf[1], kb1);
        }
        // mask multiply + truncation-split pack into A-frags
        uint32_t ah[4][4], al[4][4];
#pragma unroll
        for (int nt = 0; nt < 8; nt++) {
            const float* mp0 = maskh + (size_t)r0c * L_ + j0 + nt * 8 + 2 * (lane & 3);
            const float* mp1 = maskh + (size_t)r1c * L_ + j0 + nt * 8 + 2 * (lane & 3);
            float2 m0 = __ldg((const float2*)mp0);
            float2 m1 = __ldg((const float2*)mp1);
            float c0 = sc[nt][0] * m0.x, c1 = sc[nt][1] * m0.y;
            float c2 = sc[nt][2] * m1.x, c3 = sc[nt][3] * m1.y;
            uint32_t u0 = __float_as_uint(c0), u1 = __float_as_uint(c1);
            uint32_t u2 = __float_as_uint(c2), u3 = __float_as_uint(c3);
            int ki = nt >> 1, pspos = (nt & 1) * 2;
            ah[ki][pspos]     = __byte_perm(u0, u1, 0x7632);
            ah[ki][pspos + 1] = __byte_perm(u2, u3, 0x7632);
            float l0 = c0 - __uint_as_float(u0 & 0xFFFF0000u);
            float l1 = c1 - __uint_as_float(u1 & 0xFFFF0000u);
            float l2 = c2 - __uint_as_float(u2 & 0xFFFF0000u);
            float l3 = c3 - __uint_as_float(u3 & 0xFFFF0000u);
            al[ki][pspos]     = cvtbf2(l1, l0);
            al[ki][pspos + 1] = cvtbf2(l3, l2);
        }
        // AV: D += Ah*Vh + Al*Vh + Ah*Vl
#pragma unroll
        for (int ki = 0; ki < 4; ki++) {
#pragma unroll
            for (int nt = 0; nt < 8; nt++) {
                uint32_t vh2[2], vl2[2];
                ldmx2t(vh_b + ((ki * 16 + b_row) * 72 + nt * 8) * 2, vh2);
                ldmx2t(vl_b + ((ki * 16 + b_row) * 72 + nt * 8) * 2, vl2);
                mma16816(accv[nt], ah[ki], vh2);
                mma16816(accv[nt], al[ki], vh2);
                mma16816(accv[nt], ah[ki], vl2);
            }
        }
    }

    // epilogue
    const int rl = mi + (lane >> 2);
    const int gi0 = i0 + rl, gi1 = gi0 + 8;
    float n0 = 0.0f, n1 = 0.0f;
#pragma unroll
    for (int m = 0; m < 8; m++) {
        n0 += Qs[rl][m] * KS[m];
        n1 += Qs[rl + 8][m] * KS[m];
    }
    float rn0 = 1.0f / n0, rn1 = 1.0f / n1;
#pragma unroll
    for (int nt = 0; nt < 8; nt++) {
        int col = nt * 8 + 2 * (lane & 3);
        if (gi0 < L_) {
            float* o0 = out + (((size_t)b * L_ + gi0) * H_ + h) * D_ + col;
            *(float2*)o0 = make_float2(accv[nt][0] * rn0, accv[nt][1] * rn0);
        }
        if (gi1 < L_) {
            float* o1 = out + (((size_t)b * L_ + gi1) * H_ + h) * D_ + col;
            *(float2*)o1 = make_float2(accv[nt][2] * rn1, accv[nt][3] * rn1);
        }
    }
}

// ============================================================
extern "C" void kernel_launch(void* const* d_in, const int* in_sizes, int n_in,
                              void* d_out, int out_size) {
    const float* q    = (const float*)d_in[0];
    const float* k    = (const float*)d_in[1];
    const float* v    = (const float*)d_in[2];
    const float* proj = (const float*)d_in[3];
    const float* mask = (const float*)d_in[4];
    float* out = (float*)d_out;

    {
        dim3 grid(8, H_);
        cmask_part_kernel<<<grid, 576>>>(mask);
    }
    {
        dim3 grid(9, H_, B_);
        prep_kernel<<<grid, 128>>>(q, k, v, proj);
    }
    {
        dim3 grid(5, H_, B_);
        attn_kernel<<<grid, 256>>>(mask, out);
    }
}

// round 10
// speedup vs baseline: 3.7616x; 1.0527x over previous
#include <cuda_runtime.h>
#include <cuda_bf16.h>
#include <cstdint>

#define B_ 16
#define L_ 576
#define H_ 12
#define D_ 64
#define M_ 8
#define NUM_STAB 1e-3f
#define RATIO 0.35355339059327373f   /* 1/sqrt(M) */
#define NCH 24   /* cmask chunks */

// -------- scratch (device globals: no allocation allowed) --------
__device__ float g_qp[B_ * H_ * L_ * M_];           // q' fp32 [bh][l][8]
__device__ float g_cmp[NCH * H_ * L_];              // mask column-sum partials
__device__ float g_ksp[B_ * H_ * 9 * M_];           // ks partials [bh][ch][8]
__device__ __align__(16) __nv_bfloat16 g_qe[B_ * H_ * L_ * 32];  // [bh][l][32]=[qhi,qhi,qlo,0]
__device__ __align__(16) __nv_bfloat16 g_kt[B_ * H_ * 32 * L_];  // [bh][k=32][l]=[khi,klo,khi,0]
__device__ __align__(16) __nv_bfloat16 g_vh[B_ * H_ * L_ * 64];
__device__ __align__(16) __nv_bfloat16 g_vl[B_ * H_ * L_ * 64];

// -------- helpers --------
__device__ __forceinline__ void ldmx4(uint32_t addr, uint32_t* r) {
    asm volatile("ldmatrix.sync.aligned.m8n8.x4.shared.b16 {%0,%1,%2,%3}, [%4];"
                 : "=r"(r[0]), "=r"(r[1]), "=r"(r[2]), "=r"(r[3]) : "r"(addr));
}
__device__ __forceinline__ void ldmx4t(uint32_t addr, uint32_t* r) {
    asm volatile("ldmatrix.sync.aligned.m8n8.x4.trans.shared.b16 {%0,%1,%2,%3}, [%4];"
                 : "=r"(r[0]), "=r"(r[1]), "=r"(r[2]), "=r"(r[3]) : "r"(addr));
}
__device__ __forceinline__ void mma16816(float* c, const uint32_t* a, const uint32_t* b) {
    asm volatile("mma.sync.aligned.m16n8k16.row.col.f32.bf16.bf16.f32 "
                 "{%0,%1,%2,%3}, {%4,%5,%6,%7}, {%8,%9}, {%0,%1,%2,%3};"
                 : "+f"(c[0]), "+f"(c[1]), "+f"(c[2]), "+f"(c[3])
                 : "r"(a[0]), "r"(a[1]), "r"(a[2]), "r"(a[3]), "r"(b[0]), "r"(b[1]));
}
__device__ __forceinline__ uint32_t cvtbf2(float hi, float lo) {
    uint32_t r; asm("cvt.rn.bf16x2.f32 %0, %1, %2;" : "=r"(r) : "f"(hi), "f"(lo)); return r;
}
__device__ __forceinline__ unsigned short f2bf(float x) {
    unsigned short u; asm("cvt.rn.bf16.f32 %0, %1;" : "=h"(u) : "f"(x)); return u;
}
__device__ __forceinline__ uint32_t smem_u32(const void* p) {
    return (uint32_t)__cvta_generic_to_shared(p);
}

// ============================================================
// Kernel 1: partial column sums of mask, 24 chunks x 24 rows (288 CTAs)
// ============================================================
__global__ void __launch_bounds__(576) cmask_part_kernel(const float* __restrict__ mask) {
    int j  = threadIdx.x;
    int h  = blockIdx.y, ch = blockIdx.x;
    const float* mp = mask + ((size_t)h * L_ + ch * 24) * L_ + j;
    float s = 0.0f;
#pragma unroll 8
    for (int i = 0; i < 24; i++) s += mp[(size_t)i * L_];
    g_cmp[(ch * H_ + h) * L_ + j] = s;
}

// ============================================================
// Kernel 2: fused prep (as r9; cmask partial count updated)
// ============================================================
__global__ void __launch_bounds__(128) prep_kernel(const float* __restrict__ q,
                                                   const float* __restrict__ k,
                                                   const float* __restrict__ v,
                                                   const float* __restrict__ proj) {
    __shared__ float ps[8][68];
    __shared__ float xs[64][68];
    __shared__ unsigned short kt[32][64];
    __shared__ float red[64][8];
    __shared__ float cm[64];

    const int ch = blockIdx.x, h = blockIdx.y, b = blockIdx.z;
    const int bh = b * H_ + h, l0 = ch * 64;
    const int tid = threadIdx.x;
    const int r = tid >> 1, hf = tid & 1;

    {
        float4 pv = ((const float4*)proj)[tid];
        ps[tid >> 4][(tid & 15) * 4 + 0] = pv.x;
        ps[tid >> 4][(tid & 15) * 4 + 1] = pv.y;
        ps[tid >> 4][(tid & 15) * 4 + 2] = pv.z;
        ps[tid >> 4][(tid & 15) * 4 + 3] = pv.w;
    }
    if (tid < 64) {
        float s = 0.0f;
#pragma unroll
        for (int c2 = 0; c2 < NCH; c2++) s += g_cmp[(c2 * H_ + h) * L_ + l0 + tid];
        cm[tid] = s;
    }

    // ---------- Q ----------
#pragma unroll
    for (int iter = 0; iter < 8; iter++) {
        int idx = iter * 128 + tid;
        int rr = idx >> 4, c4 = idx & 15;
        float4 val = __ldg((const float4*)(q + (((size_t)b * L_ + l0 + rr) * H_ + h) * D_ + c4 * 4));
        *(float4*)&xs[rr][c4 * 4] = val;
    }
    __syncthreads();
    {
        float f[4];
#pragma unroll
        for (int e = 0; e < 4; e++) {
            int m = hf * 4 + e;
            float acc = 0.0f;
#pragma unroll
            for (int i = 0; i < 16; i++) {
                float4 a = *(const float4*)&xs[r][i * 4];
                float4 p = *(const float4*)&ps[m][i * 4];
                acc += a.x * p.x + a.y * p.y + a.z * p.z + a.w * p.w;
            }
            f[e] = fmaxf(RATIO * acc, 0.0f) + NUM_STAB;
        }
        *(float4*)(g_qp + ((size_t)bh * L_ + l0 + r) * 8 + hf * 4) = make_float4(f[0], f[1], f[2], f[3]);
        uint32_t hi2[2], lo2[2];
#pragma unroll
        for (int e = 0; e < 2; e++) {
            uint32_t c0 = __float_as_uint(f[2 * e]), c1 = __float_as_uint(f[2 * e + 1]);
            hi2[e] = __byte_perm(c0, c1, 0x7632);
            float lo0 = f[2 * e]     - __uint_as_float(c0 & 0xFFFF0000u);
            float lo1 = f[2 * e + 1] - __uint_as_float(c1 & 0xFFFF0000u);
            lo2[e] = cvtbf2(lo1, lo0);
        }
        __nv_bfloat16* qr = g_qe + ((size_t)bh * L_ + l0 + r) * 32;
        *(uint2*)(qr + hf * 4)      = make_uint2(hi2[0], hi2[1]);
        *(uint2*)(qr + 8 + hf * 4)  = make_uint2(hi2[0], hi2[1]);
        *(uint2*)(qr + 16 + hf * 4) = make_uint2(lo2[0], lo2[1]);
        *(uint2*)(qr + 24 + hf * 4) = make_uint2(0u, 0u);
    }
    __syncthreads();

    // ---------- K ----------
#pragma unroll
    for (int iter = 0; iter < 8; iter++) {
        int idx = iter * 128 + tid;
        int rr = idx >> 4, c4 = idx & 15;
        float4 val = __ldg((const float4*)(k + (((size_t)b * L_ + l0 + rr) * H_ + h) * D_ + c4 * 4));
        *(float4*)&xs[rr][c4 * 4] = val;
    }
    __syncthreads();
    {
        float cmv = cm[r];
#pragma unroll
        for (int e = 0; e < 4; e++) {
            int m = hf * 4 + e;
            float acc = 0.0f;
#pragma unroll
            for (int i = 0; i < 16; i++) {
                float4 a = *(const float4*)&xs[r][i * 4];
                float4 p = *(const float4*)&ps[m][i * 4];
                acc += a.x * p.x + a.y * p.y + a.z * p.z + a.w * p.w;
            }
            float f = fmaxf(RATIO * acc, 0.0f) + NUM_STAB;
            uint32_t ci = __float_as_uint(f);
            unsigned short hs = (unsigned short)(ci >> 16);
            unsigned short ls = f2bf(f - __uint_as_float(ci & 0xFFFF0000u));
            int kk = hf * 4 + e;
            kt[kk][r]      = hs;
            kt[kk + 8][r]  = ls;
            kt[kk + 16][r] = hs;
            kt[kk + 24][r] = 0;
            red[r][m] = cmv * f;
        }
    }
    __syncthreads();
    {
        int kk = tid >> 2, c = (tid & 3) * 16;
        const uint4* src = (const uint4*)&kt[kk][c];
        __nv_bfloat16* dst = g_kt + ((size_t)bh * 32 + kk) * L_ + l0 + c;
        *(uint4*)dst       = src[0];
        *(uint4*)(dst + 8) = src[1];
    }
    if (tid < 8) {
        float s = 0.0f;
#pragma unroll 16
        for (int i = 0; i < 64; i++) s += red[i][tid];
        g_ksp[((size_t)bh * 9 + ch) * 8 + tid] = s;
    }

    // ---------- V ----------
#pragma unroll
    for (int iter = 0; iter < 8; iter++) {
        int idx = iter * 128 + tid;
        int rr = idx >> 4, c4 = idx & 15;
        const float4 vv = __ldg((const float4*)(v + (((size_t)b * L_ + l0 + rr) * H_ + h) * D_ + c4 * 4));
        float f[4] = {vv.x, vv.y, vv.z, vv.w};
        uint32_t u0 = __float_as_uint(f[0]), u1 = __float_as_uint(f[1]);
        uint32_t u2 = __float_as_uint(f[2]), u3 = __float_as_uint(f[3]);
        uint32_t h01 = __byte_perm(u0, u1, 0x7632);
        uint32_t h23 = __byte_perm(u2, u3, 0x7632);
        float l0f = f[0] - __uint_as_float(u0 & 0xFFFF0000u);
        float l1f = f[1] - __uint_as_float(u1 & 0xFFFF0000u);
        float l2f = f[2] - __uint_as_float(u2 & 0xFFFF0000u);
        float l3f = f[3] - __uint_as_float(u3 & 0xFFFF0000u);
        size_t o = ((size_t)bh * L_ + l0 + rr) * 64 + c4 * 4;
        *(uint2*)(g_vh + o) = make_uint2(h01, h23);
        *(uint2*)(g_vl + o) = make_uint2(cvtbf2(l1f, l0f), cvtbf2(l3f, l2f));
    }
}

// ============================================================
// Kernel 3: fused attention. grid (5, H, B), 256 thr / 8 warps.
// ldmatrix.x4.trans for Kt/V (half the LDSM issues); register
// double-buffered tile staging.
// ============================================================
__global__ void __launch_bounds__(256, 2)
attn_kernel(const float* __restrict__ mask, float* __restrict__ out) {
    __shared__ __nv_bfloat16 Vh[64][72], Vl[64][72], Kt[32][72];
    __shared__ __nv_bfloat16 Qe[128][40];
    __shared__ float Qs[128][8];
    __shared__ float KS[8];

    const int it = blockIdx.x, h = blockIdx.y, b = blockIdx.z;
    const int i0 = it * 128, bh = b * H_ + h;
    const int tid = threadIdx.x, wid = tid >> 5, lane = tid & 31;
    const int mi = wid * 16;

    {
        int rr = tid >> 1, part = tid & 1;
        int gi = min(i0 + rr, L_ - 1);
        ((float4*)&Qs[rr][0])[part] =
            *(const float4*)(g_qp + ((size_t)bh * L_ + gi) * 8 + part * 4);
    }
    if (tid < 8) {
        float s = 0.0f;
#pragma unroll
        for (int c2 = 0; c2 < 9; c2++) s += g_ksp[((size_t)bh * 9 + c2) * 8 + tid];
        KS[tid] = s;
    }
#pragma unroll
    for (int iter = 0; iter < 2; iter++) {
        int idx = iter * 256 + tid;
        int rr = idx >> 2, c = (idx & 3) * 8;
        int gi = min(i0 + rr, L_ - 1);
        *(uint4*)&Qe[rr][c] = __ldg((const uint4*)(g_qe + ((size_t)bh * L_ + gi) * 32 + c));
    }
    __syncthreads();

    const int lq = lane >> 3, lr = lane & 7;
    const int a_row = lr + ((lq & 1) << 3);
    const int a_col = (lq & 2) << 2;
    // x4.trans addressing: rows within 16-k block + 0/8 col select
    const int vrow = ((lane >> 3) & 1) * 8 + lr;
    const int vcol = ((lane >> 4) & 1) * 8;

    const uint32_t qe_b = smem_u32(Qe);
    const uint32_t vh_b = smem_u32(Vh);
    const uint32_t vl_b = smem_u32(Vl);
    const uint32_t kt_b = smem_u32(Kt);

    uint32_t qf[2][4];
    ldmx4(qe_b + ((mi + a_row) * 40 + a_col) * 2, qf[0]);
    ldmx4(qe_b + ((mi + a_row) * 40 + 16 + a_col) * 2, qf[1]);

    float accv[8][4];
#pragma unroll
    for (int n = 0; n < 8; n++)
#pragma unroll
        for (int c = 0; c < 4; c++) accv[n][c] = 0.0f;

    const float* maskh = mask + (size_t)h * L_ * L_;
    const int r0c = min(i0 + mi + (lane >> 2), L_ - 1);
    const int r1c = min(i0 + mi + (lane >> 2) + 8, L_ - 1);

    // staging indices (per thread, fixed)
    const int v_r0 = tid >> 3,        v_c = (tid & 7) * 8;   // iter0: rows 0..31
    const int v_r1 = (256 + tid) >> 3;                       // iter1: rows 32..63
    const int k_r = tid >> 3,         k_c = (tid & 7) * 8;

    // prefetch tile jt=0
    uint4 pvh0, pvh1, pvl0, pvl1, pkt;
    {
        size_t o0 = ((size_t)bh * L_ + v_r0) * 64 + v_c;
        size_t o1 = ((size_t)bh * L_ + v_r1) * 64 + v_c;
        pvh0 = __ldg((const uint4*)(g_vh + o0));
        pvh1 = __ldg((const uint4*)(g_vh + o1));
        pvl0 = __ldg((const uint4*)(g_vl + o0));
        pvl1 = __ldg((const uint4*)(g_vl + o1));
        pkt  = __ldg((const uint4*)(g_kt + ((size_t)bh * 32 + k_r) * L_ + k_c));
    }

    for (int jt = 0; jt < 9; jt++) {
        const int j0 = jt * 64;
        __syncthreads();
        // commit prefetched tile
        *(uint4*)&Vh[v_r0][v_c] = pvh0;
        *(uint4*)&Vh[v_r1][v_c] = pvh1;
        *(uint4*)&Vl[v_r0][v_c] = pvl0;
        *(uint4*)&Vl[v_r1][v_c] = pvl1;
        *(uint4*)&Kt[k_r][k_c]  = pkt;
        __syncthreads();
        // prefetch next
        if (jt < 8) {
            const int jn = j0 + 64;
            size_t o0 = ((size_t)bh * L_ + jn + v_r0) * 64 + v_c;
            size_t o1 = ((size_t)bh * L_ + jn + v_r1) * 64 + v_c;
            pvh0 = __ldg((const uint4*)(g_vh + o0));
            pvh1 = __ldg((const uint4*)(g_vh + o1));
            pvl0 = __ldg((const uint4*)(g_vl + o0));
            pvl1 = __ldg((const uint4*)(g_vl + o1));
            pkt  = __ldg((const uint4*)(g_kt + ((size_t)bh * 32 + k_r) * L_ + jn + k_c));
        }

        // ---- S via HMMA (x4t Kt loads feed 2 n-frags each) ----
        float sc[8][4];
#pragma unroll
        for (int ntp = 0; ntp < 4; ntp++) {
            uint32_t kb0[4], kb1[4];
            ldmx4t(kt_b + (vrow * 72 + ntp * 16 + vcol) * 2, kb0);
            ldmx4t(kt_b + ((16 + vrow) * 72 + ntp * 16 + vcol) * 2, kb1);
#pragma unroll
            for (int e = 0; e < 2; e++) {
                int nt = ntp * 2 + e;
                sc[nt][0] = sc[nt][1] = sc[nt][2] = sc[nt][3] = 0.0f;
                mma16816(sc[nt], qf[0], &kb0[e * 2]);
                mma16816(sc[nt], qf[1], &kb1[e * 2]);
            }
        }
        // ---- mask multiply + truncation-split pack ----
        uint32_t ah[4][4], al[4][4];
#pragma unroll
        for (int nt = 0; nt < 8; nt++) {
            const float* mp0 = maskh + (size_t)r0c * L_ + j0 + nt * 8 + 2 * (lane & 3);
            const float* mp1 = maskh + (size_t)r1c * L_ + j0 + nt * 8 + 2 * (lane & 3);
            float2 m0 = __ldg((const float2*)mp0);
            float2 m1 = __ldg((const float2*)mp1);
            float c0 = sc[nt][0] * m0.x, c1 = sc[nt][1] * m0.y;
            float c2 = sc[nt][2] * m1.x, c3 = sc[nt][3] * m1.y;
            uint32_t u0 = __float_as_uint(c0), u1 = __float_as_uint(c1);
            uint32_t u2 = __float_as_uint(c2), u3 = __float_as_uint(c3);
            int ki = nt >> 1, pspos = (nt & 1) * 2;
            ah[ki][pspos]     = __byte_perm(u0, u1, 0x7632);
            ah[ki][pspos + 1] = __byte_perm(u2, u3, 0x7632);
            float l0 = c0 - __uint_as_float(u0 & 0xFFFF0000u);
            float l1 = c1 - __uint_as_float(u1 & 0xFFFF0000u);
            float l2 = c2 - __uint_as_float(u2 & 0xFFFF0000u);
            float l3 = c3 - __uint_as_float(u3 & 0xFFFF0000u);
            al[ki][pspos]     = cvtbf2(l1, l0);
            al[ki][pspos + 1] = cvtbf2(l3, l2);
        }
        // ---- AV: D += Ah*Vh + Al*Vh + Ah*Vl (x4t V loads) ----
#pragma unroll
        for (int ki = 0; ki < 4; ki++) {
#pragma unroll
            for (int ntp = 0; ntp < 4; ntp++) {
                uint32_t vh4[4], vl4[4];
                ldmx4t(vh_b + ((ki * 16 + vrow) * 72 + ntp * 16 + vcol) * 2, vh4);
                ldmx4t(vl_b + ((ki * 16 + vrow) * 72 + ntp * 16 + vcol) * 2, vl4);
#pragma unroll
                for (int e = 0; e < 2; e++) {
                    int nt = ntp * 2 + e;
                    mma16816(accv[nt], ah[ki], &vh4[e * 2]);
                    mma16816(accv[nt], al[ki], &vh4[e * 2]);
                    mma16816(accv[nt], ah[ki], &vl4[e * 2]);
                }
            }
        }
    }

    // epilogue
    const int rl = mi + (lane >> 2);
    const int gi0 = i0 + rl, gi1 = gi0 + 8;
    float n0 = 0.0f, n1 = 0.0f;
#pragma unroll
    for (int m = 0; m < 8; m++) {
        n0 += Qs[rl][m] * KS[m];
        n1 += Qs[rl + 8][m] * KS[m];
    }
    float rn0 = 1.0f / n0, rn1 = 1.0f / n1;
#pragma unroll
    for (int nt = 0; nt < 8; nt++) {
        int col = nt * 8 + 2 * (lane & 3);
        if (gi0 < L_) {
            float* o0 = out + (((size_t)b * L_ + gi0) * H_ + h) * D_ + col;
            *(float2*)o0 = make_float2(accv[nt][0] * rn0, accv[nt][1] * rn0);
        }
        if (gi1 < L_) {
            float* o1 = out + (((size_t)b * L_ + gi1) * H_ + h) * D_ + col;
            *(float2*)o1 = make_float2(accv[nt][2] * rn1, accv[nt][3] * rn1);
        }
    }
}

// ============================================================
extern "C" void kernel_launch(void* const* d_in, const int* in_sizes, int n_in,
                              void* d_out, int out_size) {
    const float* q    = (const float*)d_in[0];
    const float* k    = (const float*)d_in[1];
    const float* v    = (const float*)d_in[2];
    const float* proj = (const float*)d_in[3];
    const float* mask = (const float*)d_in[4];
    float* out = (float*)d_out;

    {
        dim3 grid(NCH, H_);
        cmask_part_kernel<<<grid, 576>>>(mask);
    }
    {
        dim3 grid(9, H_, B_);
        prep_kernel<<<grid, 128>>>(q, k, v, proj);
    }
    {
        dim3 grid(5, H_, B_);
        attn_kernel<<<grid, 256>>>(mask, out);
    }
}